// round 1
// baseline (speedup 1.0000x reference)
#include <cuda_runtime.h>

#define Hdim 128
#define SX 260   // Xs row stride (floats): holds up to 256-dim layer-0 input (+tail/pad)
#define SH 132   // Hs row stride (floats)

// ---------------------------------------------------------------------------
// One dense layer: out[r, c] = relu?(bias[c] + sum_k in[r,k] * W[k,c])
// Warp-private: each warp owns RPW rows; lane owns 4 consecutive output cols.
// W is (K x 128) row-major in global (L1/L2-resident, broadcast across warps).
// ---------------------------------------------------------------------------
template<int RPW, bool RELU>
__device__ __forceinline__ void mlp_layer(
    const float* __restrict__ W, const float* __restrict__ B,
    const float* __restrict__ ins, int istride, int K,
    float* __restrict__ outs, int ostride, int r0, int c0)
{
    float4 bv = *(const float4*)(B + c0);
    float4 acc[RPW];
#pragma unroll
    for (int i = 0; i < RPW; i++) acc[i] = bv;

    const float* ip[RPW];
#pragma unroll
    for (int i = 0; i < RPW; i++) ip[i] = ins + (r0 + i) * istride;

    int Kmain = K & ~3;
    for (int k = 0; k < Kmain; k += 4) {
        float4 w0 = __ldg((const float4*)(W + (size_t)(k + 0) * Hdim + c0));
        float4 w1 = __ldg((const float4*)(W + (size_t)(k + 1) * Hdim + c0));
        float4 w2 = __ldg((const float4*)(W + (size_t)(k + 2) * Hdim + c0));
        float4 w3 = __ldg((const float4*)(W + (size_t)(k + 3) * Hdim + c0));
#pragma unroll
        for (int i = 0; i < RPW; i++) {
            float4 a = *(const float4*)(ip[i] + k);
            acc[i].x += a.x * w0.x + a.y * w1.x + a.z * w2.x + a.w * w3.x;
            acc[i].y += a.x * w0.y + a.y * w1.y + a.z * w2.y + a.w * w3.y;
            acc[i].z += a.x * w0.z + a.y * w1.z + a.z * w2.z + a.w * w3.z;
            acc[i].w += a.x * w0.w + a.y * w1.w + a.z * w2.w + a.w * w3.w;
        }
    }
    for (int k = Kmain; k < K; k++) {   // tail (mr: K = 129)
        float4 wv = __ldg((const float4*)(W + (size_t)k * Hdim + c0));
#pragma unroll
        for (int i = 0; i < RPW; i++) {
            float a = ip[i][k];
            acc[i].x += a * wv.x; acc[i].y += a * wv.y;
            acc[i].z += a * wv.z; acc[i].w += a * wv.w;
        }
    }
#pragma unroll
    for (int i = 0; i < RPW; i++) {
        float4 v = acc[i];
        if (RELU) {
            v.x = fmaxf(v.x, 0.f); v.y = fmaxf(v.y, 0.f);
            v.z = fmaxf(v.z, 0.f); v.w = fmaxf(v.w, 0.f);
        }
        *(float4*)(outs + (r0 + i) * ostride + c0) = v;
    }
}

// ---------------------------------------------------------------------------
// Fused gather -> 3-layer MLP -> scatter.
// mode 0 (nem):  in = [x_in[esrc[row]], efeat[row]]       (K0=256), out -> xw[edst[row]]
// mode 1 (mg):   in = [xw[esrc[s+row]], xw[esrc[s+half+row]]] (K0=256),
//                out -> xw[edst[s+half+row]]
// mode 2 (mr):   in = [xw[edst[s+row]], state]            (K0=129),
//                out: xw[esrc[s+row]] = mlp + xw[esrc[s+row]]
// mode 3 (mr leaf): like 2, but bottom read from x_in (original leaves)
// ---------------------------------------------------------------------------
template<int RPW>
__global__ void __launch_bounds__(256)
mlp_kernel(const float* __restrict__ x_in,
           float* __restrict__ xw,
           const int* __restrict__ esrc,
           const int* __restrict__ edst,
           const float* __restrict__ estates,
           const float* __restrict__ efeat,
           const float* __restrict__ W0, const float* __restrict__ B0,
           const float* __restrict__ W1, const float* __restrict__ B1,
           const float* __restrict__ W2, const float* __restrict__ B2,
           int s, int M, int half, int mode, int K0)
{
    extern __shared__ float sm[];
    const int TILE = 8 * RPW;
    float* Xs = sm;                 // [TILE][SX]
    float* Hs = sm + TILE * SX;     // [TILE][SH]

    int lane = threadIdx.x & 31;
    int warp = threadIdx.x >> 5;
    int r0 = warp * RPW;
    int grow0 = blockIdx.x * TILE + r0;
    if (grow0 >= M) return;          // whole warp has no rows
    int c0 = lane * 4;

    // ---- gather (warp-private rows; each row = 32 lanes x float4) ----
#pragma unroll
    for (int i = 0; i < RPW; i++) {
        int grow = grow0 + i;
        if (grow >= M) break;
        float* xr = Xs + (r0 + i) * SX;
        if (mode == 0) {
            int src = esrc[grow];
            ((float4*)xr)[lane]          = ((const float4*)(x_in + (size_t)src * Hdim))[lane];
            ((float4*)(xr + Hdim))[lane] = ((const float4*)(efeat + (size_t)grow * Hdim))[lane];
        } else if (mode == 1) {
            int l  = esrc[s + grow];
            int rr = esrc[s + half + grow];
            ((float4*)xr)[lane]          = ((const float4*)(xw + (size_t)l  * Hdim))[lane];
            ((float4*)(xr + Hdim))[lane] = ((const float4*)(xw + (size_t)rr * Hdim))[lane];
        } else {
            int dn = edst[s + grow];
            ((float4*)xr)[lane] = ((const float4*)(xw + (size_t)dn * Hdim))[lane];
            if (lane == 0) xr[Hdim] = estates[s + grow];
        }
    }
    __syncwarp();

    mlp_layer<RPW, true >(W0, B0, Xs, SX, K0,   Hs, SH, r0, c0);
    __syncwarp();
    mlp_layer<RPW, true >(W1, B1, Hs, SH, Hdim, Xs, SX, r0, c0);
    __syncwarp();
    mlp_layer<RPW, false>(W2, B2, Xs, SX, Hdim, Hs, SH, r0, c0);
    __syncwarp();

    // ---- scatter ----
#pragma unroll
    for (int i = 0; i < RPW; i++) {
        int grow = grow0 + i;
        if (grow >= M) break;
        float4 v = *(float4*)(Hs + (r0 + i) * SH + c0);
        int node;
        if (mode == 0)      node = edst[grow];
        else if (mode == 1) node = edst[s + half + grow];
        else                node = esrc[s + grow];
        if (mode >= 2) {
            const float* bot = (mode == 3 ? x_in : xw) + (size_t)node * Hdim;
            float4 bv = *(const float4*)(bot + c0);
            v.x += bv.x; v.y += bv.y; v.z += bv.z; v.w += bv.w;
        }
        *(float4*)(xw + (size_t)node * Hdim + c0) = v;
    }
}

// ---------------------------------------------------------------------------
// Host launcher
// ---------------------------------------------------------------------------
static void launch_phase(const float* x, float* xw,
                         const int* esrc, const int* edst,
                         const float* estates, const float* efeat,
                         const float* W0, const float* B0,
                         const float* W1, const float* B1,
                         const float* W2, const float* B2,
                         long s, int M, int half, int mode, int K0)
{
    if (M <= 0) return;
    if (M >= 64) {
        int grid = (M + 63) / 64;
        size_t smem = (size_t)(64 * SX + 64 * SH) * 4;
        mlp_kernel<8><<<grid, 256, smem>>>(x, xw, esrc, edst, estates, efeat,
                                           W0, B0, W1, B1, W2, B2,
                                           (int)s, M, half, mode, K0);
    } else {
        int grid = (M + 7) / 8;
        size_t smem = (size_t)(8 * SX + 8 * SH) * 4;
        mlp_kernel<1><<<grid, 256, smem>>>(x, xw, esrc, edst, estates, efeat,
                                           W0, B0, W1, B1, W2, B2,
                                           (int)s, M, half, mode, K0);
    }
}

extern "C" void kernel_launch(void* const* d_in, const int* in_sizes, int n_in,
                              void* d_out, int out_size)
{
    (void)out_size;
    const float* x       = (const float*)d_in[0];
    const int*   esrc    = (const int*)  d_in[1];
    const int*   edst    = (const int*)  d_in[2];
    const float* estates = (const float*)d_in[3];
    const float* efeat   = (const float*)d_in[4];

    // Weights: the 18 non-scalar tensors after index 4, in order
    // (nem w0,b0,w1,b1,w2,b2 ; mg ... ; mr ...). gcmn_depth is the lone
    // size-1 entry (position varies by metadata ordering) -> skip it.
    const float* Wt[18];
    int wi = 0;
    for (int i = 5; i < n_in && wi < 18; i++) {
        if (in_sizes[i] == 1) continue;
        Wt[wi++] = (const float*)d_in[i];
    }
    const float *nw0 = Wt[0],  *nb0 = Wt[1],  *nw1 = Wt[2],  *nb1 = Wt[3],
                *nw2 = Wt[4],  *nb2 = Wt[5];
    const float *gw0 = Wt[6],  *gb0 = Wt[7],  *gw1 = Wt[8],  *gb1 = Wt[9],
                *gw2 = Wt[10], *gb2 = Wt[11];
    const float *rw0 = Wt[12], *rb0 = Wt[13], *rw1 = Wt[14], *rb1 = Wt[15],
                *rw2 = Wt[16], *rb2 = Wt[17];

    int  nL      = in_sizes[4] / Hdim;       // B * N_LEAF
    long n_edges = (long)in_sizes[1];

    // Derive tree depth D from edge counts: n_edges = nL + sum_{d=1..D-1} nL>>(d-1)
    int Dn = 1; long off = (long)nL;
    while (off < n_edges && Dn < 40) { off += (long)(nL >> (Dn - 1)); Dn++; }

    // Block offsets for per-depth edge ranges
    long boff[48]; boff[0] = 0;
    { long o = nL; for (int d = 1; d < Dn; d++) { boff[d] = o; o += (long)(nL >> (d - 1)); } }

    float* xw = (float*)d_out;   // working buffer == output; every node gets written

    // Allow >48KB dynamic smem for the big-tile kernel
    cudaFuncSetAttribute(mlp_kernel<8>, cudaFuncAttributeMaxDynamicSharedMemorySize,
                         (64 * SX + 64 * SH) * 4);

    // Phase 1: nem over all leaf edges (reads original x for leaves)
    launch_phase(x, xw, esrc, edst, estates, efeat,
                 nw0, nb0, nw1, nb1, nw2, nb2, 0, nL, 0, 0, 256);

    // Phase 2: up-sweep (mg), levels d = 1 .. D-1
    for (int d = 1; d < Dn; d++) {
        int m = nL >> (d - 1);
        launch_phase(x, xw, esrc, edst, estates, efeat,
                     gw0, gb0, gw1, gb1, gw2, gb2, boff[d], m / 2, m / 2, 1, 256);
    }

    // Phase 3: down-sweep (mr), depth = D .. 1
    for (int depth = Dn; depth >= 1; depth--) {
        long s; int m;
        if (depth == 1) { s = 0; m = nL; }
        else            { s = boff[depth - 1]; m = nL >> (depth - 2); }
        launch_phase(x, xw, esrc, edst, estates, efeat,
                     rw0, rb0, rw1, rb1, rw2, rb2, s, m, 0,
                     depth == 1 ? 3 : 2, Hdim + 1);
    }
}